// round 1
// baseline (speedup 1.0000x reference)
#include <cuda_runtime.h>
#include <cuda_bf16.h>
#include <math.h>

// Problem constants
#define BATCH       32768
#define DIM         128
#define NCENT       6400     // 100 * 64
#define KC          64       // clusters per class
#define TM          128      // rows per block
#define TN          128      // centers per chunk
#define NTHREADS    256

// smem layout (floats):
//   xs : [DIM][129]  k-major transposed x tile       offset 0
//   cs : [DIM][129]  k-major transposed center tile  offset 16512
//   x2s: [TM]                                         offset 33024
// reduction aliases (after main loop, xs region reused):
//   rv : [TM][16] float   offset 0
//   ri : [TM][16] int     offset 2048
//   rowIdx: [TM] int      offset 4096
#define XS_OFF   0
#define CS_OFF   (128 * 129)
#define X2_OFF   (2 * 128 * 129)
#define SMEM_FLOATS (2 * 128 * 129 + 128)
#define SMEM_BYTES  (SMEM_FLOATS * 4)

__device__ float g_c2[NCENT];

// ---------------------------------------------------------------------------
// Kernel 0: squared norms of all centers. One warp per center.
// ---------------------------------------------------------------------------
__global__ void c2_kernel(const float* __restrict__ centers) {
    int warp = (blockIdx.x * blockDim.x + threadIdx.x) >> 5;
    int lane = threadIdx.x & 31;
    if (warp >= NCENT) return;
    float4 v = reinterpret_cast<const float4*>(centers)[warp * (DIM / 4) + lane];
    float s = v.x * v.x + v.y * v.y + v.z * v.z + v.w * v.w;
#pragma unroll
    for (int off = 16; off > 0; off >>= 1)
        s += __shfl_xor_sync(0xFFFFFFFFu, s, off);
    if (lane == 0) g_c2[warp] = s;
}

// ---------------------------------------------------------------------------
// Kernel 1: fused distance-GEMM + argmin + gather epilogue.
// Block = 128 rows. Loop over 50 chunks of 128 centers.
// Thread (tx,ty) 16x16 grid; micro-tile: rows ty+16*i, cols tx+16*j (i,j<8).
// ---------------------------------------------------------------------------
__global__ __launch_bounds__(NTHREADS, 1)
void vq_kernel(const float* __restrict__ x,
               const float* __restrict__ centers,
               float* __restrict__ out) {
    extern __shared__ float smem[];
    float* xs  = smem + XS_OFF;
    float* cs  = smem + CS_OFF;
    float* x2s = smem + X2_OFF;

    const int tid = threadIdx.x;
    const int tx = tid & 15;
    const int ty = tid >> 4;
    const int r0 = blockIdx.x * TM;

    // ---- load x tile, transposed into xs[k][m] (stride 129) ----
    {
        const float4* xg = reinterpret_cast<const float4*>(x + (size_t)r0 * DIM);
        // 128 rows * 32 float4 = 4096 float4, 16 per thread
#pragma unroll
        for (int it = 0; it < 16; it++) {
            int idx = tid + it * NTHREADS;
            int m  = idx >> 5;        // row within tile
            int k4 = idx & 31;        // float4 index along k
            float4 v = xg[m * 32 + k4];
            int kb = k4 * 4;
            xs[(kb + 0) * 129 + m] = v.x;
            xs[(kb + 1) * 129 + m] = v.y;
            xs[(kb + 2) * 129 + m] = v.z;
            xs[(kb + 3) * 129 + m] = v.w;
        }
    }
    __syncthreads();

    // ---- x2 per row ----
    if (tid < TM) {
        float s = 0.0f;
#pragma unroll 8
        for (int k = 0; k < DIM; k++) {
            float v = xs[k * 129 + tid];
            s += v * v;
        }
        x2s[tid] = s;
    }

    float bestv[8];
    int   besti[8];
#pragma unroll
    for (int i = 0; i < 8; i++) { bestv[i] = INFINITY; besti[i] = 0; }

    float x2r[8];
    // filled after first sync below (x2s written above by threads <128; need sync)

    for (int nc = 0; nc < NCENT; nc += TN) {
        __syncthreads();  // protect cs from previous iteration's readers / x2s write
        // ---- load center chunk, transposed into cs[k][m] ----
        {
            const float4* cg = reinterpret_cast<const float4*>(centers + (size_t)nc * DIM);
#pragma unroll
            for (int it = 0; it < 16; it++) {
                int idx = tid + it * NTHREADS;
                int m  = idx >> 5;
                int k4 = idx & 31;
                float4 v = cg[m * 32 + k4];
                int kb = k4 * 4;
                cs[(kb + 0) * 129 + m] = v.x;
                cs[(kb + 1) * 129 + m] = v.y;
                cs[(kb + 2) * 129 + m] = v.z;
                cs[(kb + 3) * 129 + m] = v.w;
            }
        }
        __syncthreads();

        if (nc == 0) {
#pragma unroll
            for (int i = 0; i < 8; i++) x2r[i] = x2s[ty + 16 * i];
        }

        float acc[8][8];
#pragma unroll
        for (int i = 0; i < 8; i++)
#pragma unroll
            for (int j = 0; j < 8; j++) acc[i][j] = 0.0f;

#pragma unroll 4
        for (int k = 0; k < DIM; k++) {
            float xf[8], cf[8];
#pragma unroll
            for (int i = 0; i < 8; i++) xf[i] = xs[k * 129 + ty + 16 * i];
#pragma unroll
            for (int j = 0; j < 8; j++) cf[j] = cs[k * 129 + tx + 16 * j];
#pragma unroll
            for (int i = 0; i < 8; i++)
#pragma unroll
                for (int j = 0; j < 8; j++)
                    acc[i][j] = fmaf(xf[i], cf[j], acc[i][j]);
        }

        // fold into running argmin:  sq = (x2 + c2) - 2*dot  (matches ref rounding)
#pragma unroll
        for (int j = 0; j < 8; j++) {
            int col = nc + tx + 16 * j;
            float c2 = __ldg(&g_c2[col]);
#pragma unroll
            for (int i = 0; i < 8; i++) {
                float t  = x2r[i] + c2;
                float sq = t - 2.0f * acc[i][j];
                if (sq < bestv[i]) { bestv[i] = sq; besti[i] = col; }
            }
        }
    }

    __syncthreads();
    // ---- cross-thread reduction over the 16 tx lanes per row ----
    float* rv = smem;                                   // [128][16]
    int*   ri = reinterpret_cast<int*>(smem + 2048);    // [128][16]
    int*   rowIdx = reinterpret_cast<int*>(smem + 4096);// [128]
#pragma unroll
    for (int i = 0; i < 8; i++) {
        int row = ty + 16 * i;
        rv[row * 16 + tx] = bestv[i];
        ri[row * 16 + tx] = besti[i];
    }
    __syncthreads();

    if (tid < TM) {
        int row = tid;
        float bv = rv[row * 16 + 0];
        int   bi = ri[row * 16 + 0];
#pragma unroll
        for (int t = 1; t < 16; t++) {
            float v = rv[row * 16 + t];
            int   id = ri[row * 16 + t];
            if (v < bv || (v == bv && id < bi)) { bv = v; bi = id; }
        }
        rowIdx[row] = bi;
        int g = r0 + row;
        float* outAssign = out + (size_t)BATCH * DIM;
        float* outDist   = out + (size_t)BATCH * DIM + BATCH;
        float* outClass  = out + (size_t)BATCH * DIM + 2 * BATCH;
        outAssign[g] = (float)(bi % KC);
        outDist[g]   = sqrtf(fmaxf(bv, 0.0f));
        outClass[g]  = (float)(bi / KC);
    }
    __syncthreads();

    // ---- gather quantized = centers[argmin] ----
    {
        const float4* cg = reinterpret_cast<const float4*>(centers);
        float4* og = reinterpret_cast<float4*>(out);
#pragma unroll
        for (int it = 0; it < 16; it++) {
            int n = tid + it * NTHREADS;      // 0..4095
            int row = n >> 5;
            int c4  = n & 31;
            float4 v = cg[(size_t)rowIdx[row] * 32 + c4];
            og[(size_t)(r0 + row) * 32 + c4] = v;
        }
    }
}

extern "C" void kernel_launch(void* const* d_in, const int* in_sizes, int n_in,
                              void* d_out, int out_size) {
    const float* x       = (const float*)d_in[0];
    const float* centers = (const float*)d_in[1];
    // d_in[2] = labels (int64), unused by the forward outputs
    float* out = (float*)d_out;

    cudaFuncSetAttribute(vq_kernel, cudaFuncAttributeMaxDynamicSharedMemorySize, SMEM_BYTES);

    c2_kernel<<<(NCENT * 32 + 255) / 256, 256>>>(centers);
    vq_kernel<<<BATCH / TM, NTHREADS, SMEM_BYTES>>>(x, centers, out);
}

// round 3
// speedup vs baseline: 2.1701x; 2.1701x over previous
#include <cuda_runtime.h>
#include <cuda_bf16.h>
#include <math.h>
#include <stdint.h>

// ---------------- problem constants ----------------
#define BATCH     32768
#define DIM       128
#define NCENT     6400
#define KC        64
#define AMT       (BATCH / 16)     // 2048 A row-tiles (m16)
#define BNT       (NCENT / 8)      // 800  B col-tiles (n8)
#define NCHUNK    50               // chunks of 128 centers

// ---------------- device scratch (fragment-layout split planes) ------------
// A frag tile (m16 x k16): 32 lanes x uint4 (4 b32 = 8 bf16)
// B frag tile (k16 x n8):  32 lanes x uint2 (2 b32 = 4 bf16)
__device__ uint4 g_asplit[3][AMT][8][32];   // 25.2 MB
__device__ uint2 g_bsplit[3][BNT][8][32];   // 4.9 MB
__device__ float g_c2[NCENT];
__device__ float g_x2[BATCH];

// ---------------- helpers ----------------
__device__ __forceinline__ uint32_t packbf(float lo, float hi) {
    __nv_bfloat162 h = __floats2bfloat162_rn(lo, hi);
    return *reinterpret_cast<uint32_t*>(&h);
}
// 3-way bf16 split: v = a + b + c_fp32, planes rounded to bf16.
struct Split3 { float a, b, c; };
__device__ __forceinline__ Split3 split3(float v) {
    Split3 s;
    s.a = __bfloat162float(__float2bfloat16(v));
    float e1 = v - s.a;
    s.b = __bfloat162float(__float2bfloat16(e1));
    s.c = e1 - s.b;              // rounded to bf16 when packed
    return s;
}
__device__ __forceinline__ float planeof(const Split3& s, int p) {
    return p == 0 ? s.a : (p == 1 ? s.b : s.c);
}

__device__ __forceinline__ void mma16816(float* d, const uint4& a, const uint2& b) {
    asm volatile(
        "mma.sync.aligned.m16n8k16.row.col.f32.bf16.bf16.f32 "
        "{%0,%1,%2,%3}, {%4,%5,%6,%7}, {%8,%9}, {%0,%1,%2,%3};"
        : "+f"(d[0]), "+f"(d[1]), "+f"(d[2]), "+f"(d[3])
        : "r"(a.x), "r"(a.y), "r"(a.z), "r"(a.w), "r"(b.x), "r"(b.y));
}

// ---------------------------------------------------------------------------
// norms: one warp per vector (shared by x2 and c2)
// ---------------------------------------------------------------------------
__global__ void norm_kernel(const float* __restrict__ v, float* __restrict__ out, int n) {
    int warp = (blockIdx.x * blockDim.x + threadIdx.x) >> 5;
    int lane = threadIdx.x & 31;
    if (warp >= n) return;
    float4 q = reinterpret_cast<const float4*>(v)[warp * (DIM / 4) + lane];
    float s = q.x * q.x + q.y * q.y + q.z * q.z + q.w * q.w;
#pragma unroll
    for (int off = 16; off > 0; off >>= 1)
        s += __shfl_xor_sync(0xFFFFFFFFu, s, off);
    if (lane == 0) out[warp] = s;
}

// ---------------------------------------------------------------------------
// prep A: x -> 3 bf16 planes in mma A-fragment layout
// thread = (Mtile, ktile, lane)
// ---------------------------------------------------------------------------
__global__ void prep_a_kernel(const float* __restrict__ x) {
    int idx = blockIdx.x * blockDim.x + threadIdx.x;   // 2048*8*32
    int M  = idx >> 8;
    int kt = (idx >> 5) & 7;
    int l  = idx & 31;
    int g = l >> 2, t = l & 3;
    int r0 = M * 16 + g, r1 = r0 + 8;
    int c0 = kt * 16 + 2 * t;
    float2 v00 = *reinterpret_cast<const float2*>(x + (size_t)r0 * DIM + c0);
    float2 v10 = *reinterpret_cast<const float2*>(x + (size_t)r1 * DIM + c0);
    float2 v02 = *reinterpret_cast<const float2*>(x + (size_t)r0 * DIM + c0 + 8);
    float2 v12 = *reinterpret_cast<const float2*>(x + (size_t)r1 * DIM + c0 + 8);
    Split3 s00x = split3(v00.x), s00y = split3(v00.y);
    Split3 s10x = split3(v10.x), s10y = split3(v10.y);
    Split3 s02x = split3(v02.x), s02y = split3(v02.y);
    Split3 s12x = split3(v12.x), s12y = split3(v12.y);
#pragma unroll
    for (int p = 0; p < 3; p++) {
        uint4 r;
        r.x = packbf(planeof(s00x, p), planeof(s00y, p));
        r.y = packbf(planeof(s10x, p), planeof(s10y, p));
        r.z = packbf(planeof(s02x, p), planeof(s02y, p));
        r.w = packbf(planeof(s12x, p), planeof(s12y, p));
        g_asplit[p][M][kt][l] = r;
    }
}

// ---------------------------------------------------------------------------
// prep B: centers -> 3 bf16 planes in mma B-fragment layout
// thread = (Ntile, ktile, lane)
// ---------------------------------------------------------------------------
__global__ void prep_b_kernel(const float* __restrict__ centers) {
    int idx = blockIdx.x * blockDim.x + threadIdx.x;   // 800*8*32
    int N  = idx >> 8;
    int kt = (idx >> 5) & 7;
    int l  = idx & 31;
    int g = l >> 2, t = l & 3;
    int n = N * 8 + g;
    int c0 = kt * 16 + 2 * t;
    float2 w0 = *reinterpret_cast<const float2*>(centers + (size_t)n * DIM + c0);
    float2 w1 = *reinterpret_cast<const float2*>(centers + (size_t)n * DIM + c0 + 8);
    Split3 s0x = split3(w0.x), s0y = split3(w0.y);
    Split3 s1x = split3(w1.x), s1y = split3(w1.y);
#pragma unroll
    for (int p = 0; p < 3; p++) {
        uint2 r;
        r.x = packbf(planeof(s0x, p), planeof(s0y, p));
        r.y = packbf(planeof(s1x, p), planeof(s1y, p));
        g_bsplit[p][N][kt][l] = r;
    }
}

// ---------------------------------------------------------------------------
// main fused kernel: 6-term split GEMM (mma.sync bf16) + argmin + outputs
// grid 256 CTAs x 128 threads; CTA tile 128 rows x 128 cols/chunk;
// warp tile 64x64 (warps 2x2); no smem in mainloop.
// ---------------------------------------------------------------------------
__global__ __launch_bounds__(128, 2)
void vq_main(const float* __restrict__ centers, float* __restrict__ out) {
    const int tid = threadIdx.x;
    const int w = tid >> 5, l = tid & 31;
    const int g = l >> 2, t = l & 3;
    const int mw = w >> 1, nw = w & 1;
    const int blk = blockIdx.x;
    const int Mb = blk * 8 + mw * 4;          // global A-tile base (of 2048)

    float x2r[8];
#pragma unroll
    for (int mt = 0; mt < 4; mt++)
#pragma unroll
        for (int h = 0; h < 2; h++)
            x2r[mt * 2 + h] = g_x2[blk * 128 + mw * 64 + mt * 16 + h * 8 + g];

    float bv[8];
    int   bi[8];
#pragma unroll
    for (int s = 0; s < 8; s++) { bv[s] = INFINITY; bi[s] = 0; }

    const uint4* __restrict__ Abase = &g_asplit[0][0][0][0];
    const uint2* __restrict__ Bbase = &g_bsplit[0][0][0][0];

    for (int ch = 0; ch < NCHUNK; ch++) {
        const int Nb = ch * 16 + nw * 8;      // global B-tile base (of 800)
        float acc[4][8][4];
#pragma unroll
        for (int mt = 0; mt < 4; mt++)
#pragma unroll
            for (int nt = 0; nt < 8; nt++)
#pragma unroll
                for (int q = 0; q < 4; q++) acc[mt][nt][q] = 0.0f;

#pragma unroll 1
        for (int term = 0; term < 6; term++) {
            int sa = (0x201100u >> (term * 4)) & 3;   // 0,0,1,1,0,2
            int sb = (0x021010u >> (term * 4)) & 3;   // 0,1,0,1,2,0
            const uint4* Ap = Abase + ((size_t)(sa * AMT + Mb) * 8) * 32 + l;
            const uint2* Bp = Bbase + ((size_t)(sb * BNT + Nb) * 8) * 32 + l;
#pragma unroll
            for (int kt = 0; kt < 8; kt++) {
                uint4 a[4];
                uint2 b[8];
#pragma unroll
                for (int mt = 0; mt < 4; mt++) a[mt] = __ldg(Ap + (size_t)mt * 256 + kt * 32);
#pragma unroll
                for (int nt = 0; nt < 8; nt++) b[nt] = __ldg(Bp + (size_t)nt * 256 + kt * 32);
#pragma unroll
                for (int mt = 0; mt < 4; mt++)
#pragma unroll
                    for (int nt = 0; nt < 8; nt++)
                        mma16816(acc[mt][nt], a[mt], b[nt]);
            }
        }

        // fold into running argmin with reference rounding: (x2 + c2) - 2*dot
#pragma unroll
        for (int nt = 0; nt < 8; nt++) {
            int col0 = ch * 128 + nw * 64 + nt * 8 + 2 * t;
            float2 c2v = *reinterpret_cast<const float2*>(&g_c2[col0]);
#pragma unroll
            for (int mt = 0; mt < 4; mt++) {
                float t00 = x2r[mt * 2 + 0] + c2v.x;
                float t01 = x2r[mt * 2 + 0] + c2v.y;
                float t10 = x2r[mt * 2 + 1] + c2v.x;
                float t11 = x2r[mt * 2 + 1] + c2v.y;
                float s00 = t00 - 2.0f * acc[mt][nt][0];
                float s01 = t01 - 2.0f * acc[mt][nt][1];
                float s10 = t10 - 2.0f * acc[mt][nt][2];
                float s11 = t11 - 2.0f * acc[mt][nt][3];
                if (s00 < bv[mt * 2 + 0]) { bv[mt * 2 + 0] = s00; bi[mt * 2 + 0] = col0; }
                if (s01 < bv[mt * 2 + 0]) { bv[mt * 2 + 0] = s01; bi[mt * 2 + 0] = col0 + 1; }
                if (s10 < bv[mt * 2 + 1]) { bv[mt * 2 + 1] = s10; bi[mt * 2 + 1] = col0; }
                if (s11 < bv[mt * 2 + 1]) { bv[mt * 2 + 1] = s11; bi[mt * 2 + 1] = col0 + 1; }
            }
        }
    }

    // reduce across the 4 quad lanes (t = 0..3 share the same rows)
#pragma unroll
    for (int s = 0; s < 8; s++) {
#pragma unroll
        for (int off = 1; off <= 2; off <<= 1) {
            float ov = __shfl_xor_sync(0xFFFFFFFFu, bv[s], off);
            int   oi = __shfl_xor_sync(0xFFFFFFFFu, bi[s], off);
            if (ov < bv[s] || (ov == bv[s] && oi < bi[s])) { bv[s] = ov; bi[s] = oi; }
        }
    }

    // cross-warp (nw pair) reduction via smem
    __shared__ float srv[2][128];
    __shared__ int   sri[2][128];
    if (t == 0) {
#pragma unroll
        for (int s = 0; s < 8; s++) {
            int row = mw * 64 + (s >> 1) * 16 + (s & 1) * 8 + g;
            srv[nw][row] = bv[s];
            sri[nw][row] = bi[s];
        }
    }
    __syncthreads();

    if (tid < 128) {
        float v0 = srv[0][tid], v1 = srv[1][tid];
        int   i0 = sri[0][tid], i1 = sri[1][tid];
        float fv = v0; int fi = i0;
        if (v1 < fv || (v1 == fv && i1 < fv)) { }   // placeholder avoided below
        if (v1 < v0 || (v1 == v0 && i1 < i0)) { fv = v1; fi = i1; }
        int gr = blk * 128 + tid;
        float* outAssign = out + (size_t)BATCH * DIM;
        float* outDist   = outAssign + BATCH;
        float* outClass  = outDist + BATCH;
        outAssign[gr] = (float)(fi % KC);
        outDist[gr]   = sqrtf(fmaxf(fv, 0.0f));
        outClass[gr]  = (float)(fi / KC);
        // gather quantized row = centers[fi]
        const float4* cg = reinterpret_cast<const float4*>(centers) + (size_t)fi * 32;
        float4* og = reinterpret_cast<float4*>(out) + (size_t)gr * 32;
#pragma unroll 8
        for (int q = 0; q < 32; q++) og[q] = cg[q];
    }
}

extern "C" void kernel_launch(void* const* d_in, const int* in_sizes, int n_in,
                              void* d_out, int out_size) {
    const float* x       = (const float*)d_in[0];
    const float* centers = (const float*)d_in[1];
    float* out = (float*)d_out;

    float* d_x2; cudaGetSymbolAddress((void**)&d_x2, g_x2);
    float* d_c2; cudaGetSymbolAddress((void**)&d_c2, g_c2);

    norm_kernel<<<(BATCH * 32 + 255) / 256, 256>>>(x, d_x2, BATCH);
    norm_kernel<<<(NCENT * 32 + 255) / 256, 256>>>(centers, d_c2, NCENT);
    prep_a_kernel<<<(AMT * 8 * 32) / 256, 256>>>(x);
    prep_b_kernel<<<(BNT * 8 * 32) / 256, 256>>>(centers);
    vq_main<<<BATCH / 128, 128>>>(centers, out);
}

// round 4
// speedup vs baseline: 3.8371x; 1.7681x over previous
#include <cuda_runtime.h>
#include <cuda_fp16.h>
#include <math.h>
#include <stdint.h>

// ---------------- problem constants ----------------
#define BATCH     32768
#define DIM       128
#define NCENT     6400
#define KC        64
#define AMT       (BATCH / 16)     // 2048 A row-tiles (m16)
#define BNT       (NCENT / 8)      // 800  B col-tiles (n8)
#define NCHUNK    50               // chunks of 128 centers

// ---------------- device scratch (fragment-layout fp16 split planes) -------
// A frag tile (m16 x k16): 32 lanes x uint4 (4 b32 = 8 fp16)
// B frag tile (k16 x n8):  32 lanes x uint2 (2 b32 = 4 fp16)
__device__ uint4 g_asplit[2][AMT][8][32];   // 16.8 MB
__device__ uint2 g_bsplit[2][BNT][8][32];   // 3.3 MB
__device__ float g_c2[NCENT];
__device__ float g_x2[BATCH];

// ---------------- helpers ----------------
__device__ __forceinline__ uint32_t packh(float lo, float hi) {
    __half2 h = __floats2half2_rn(lo, hi);
    return *reinterpret_cast<uint32_t*>(&h);
}
// 2-way fp16 split: v = a + b + eps, |eps| <= 2^-22 |v|
struct Split2 { float a, b; };
__device__ __forceinline__ Split2 split2(float v) {
    Split2 s;
    s.a = __half2float(__float2half_rn(v));
    s.b = v - s.a;                 // rounded to fp16 at pack time
    return s;
}
__device__ __forceinline__ float planeof(const Split2& s, int p) {
    return p == 0 ? s.a : s.b;
}

__device__ __forceinline__ void mma16816(float* d, const uint4& a, const uint2& b) {
    asm volatile(
        "mma.sync.aligned.m16n8k16.row.col.f32.f16.f16.f32 "
        "{%0,%1,%2,%3}, {%4,%5,%6,%7}, {%8,%9}, {%0,%1,%2,%3};"
        : "+f"(d[0]), "+f"(d[1]), "+f"(d[2]), "+f"(d[3])
        : "r"(a.x), "r"(a.y), "r"(a.z), "r"(a.w), "r"(b.x), "r"(b.y));
}

// ---------------------------------------------------------------------------
// norms: one warp per vector
// ---------------------------------------------------------------------------
__global__ void norm_kernel(const float* __restrict__ v, float* __restrict__ out, int n) {
    int warp = (blockIdx.x * blockDim.x + threadIdx.x) >> 5;
    int lane = threadIdx.x & 31;
    if (warp >= n) return;
    float4 q = reinterpret_cast<const float4*>(v)[warp * (DIM / 4) + lane];
    float s = q.x * q.x + q.y * q.y + q.z * q.z + q.w * q.w;
#pragma unroll
    for (int off = 16; off > 0; off >>= 1)
        s += __shfl_xor_sync(0xFFFFFFFFu, s, off);
    if (lane == 0) out[warp] = s;
}

// ---------------------------------------------------------------------------
// prep A: x -> 2 fp16 planes in mma A-fragment layout
// ---------------------------------------------------------------------------
__global__ void prep_a_kernel(const float* __restrict__ x) {
    int idx = blockIdx.x * blockDim.x + threadIdx.x;   // 2048*8*32
    int M  = idx >> 8;
    int kt = (idx >> 5) & 7;
    int l  = idx & 31;
    int g = l >> 2, t = l & 3;
    int r0 = M * 16 + g, r1 = r0 + 8;
    int c0 = kt * 16 + 2 * t;
    float2 v00 = *reinterpret_cast<const float2*>(x + (size_t)r0 * DIM + c0);
    float2 v10 = *reinterpret_cast<const float2*>(x + (size_t)r1 * DIM + c0);
    float2 v02 = *reinterpret_cast<const float2*>(x + (size_t)r0 * DIM + c0 + 8);
    float2 v12 = *reinterpret_cast<const float2*>(x + (size_t)r1 * DIM + c0 + 8);
    Split2 s00x = split2(v00.x), s00y = split2(v00.y);
    Split2 s10x = split2(v10.x), s10y = split2(v10.y);
    Split2 s02x = split2(v02.x), s02y = split2(v02.y);
    Split2 s12x = split2(v12.x), s12y = split2(v12.y);
#pragma unroll
    for (int p = 0; p < 2; p++) {
        uint4 r;
        r.x = packh(planeof(s00x, p), planeof(s00y, p));
        r.y = packh(planeof(s10x, p), planeof(s10y, p));
        r.z = packh(planeof(s02x, p), planeof(s02y, p));
        r.w = packh(planeof(s12x, p), planeof(s12y, p));
        g_asplit[p][M][kt][l] = r;
    }
}

// ---------------------------------------------------------------------------
// prep B: centers -> 2 fp16 planes in mma B-fragment layout
// ---------------------------------------------------------------------------
__global__ void prep_b_kernel(const float* __restrict__ centers) {
    int idx = blockIdx.x * blockDim.x + threadIdx.x;   // 800*8*32
    int N  = idx >> 8;
    int kt = (idx >> 5) & 7;
    int l  = idx & 31;
    int g = l >> 2, t = l & 3;
    int n = N * 8 + g;
    int c0 = kt * 16 + 2 * t;
    float2 w0 = *reinterpret_cast<const float2*>(centers + (size_t)n * DIM + c0);
    float2 w1 = *reinterpret_cast<const float2*>(centers + (size_t)n * DIM + c0 + 8);
    Split2 s0x = split2(w0.x), s0y = split2(w0.y);
    Split2 s1x = split2(w1.x), s1y = split2(w1.y);
#pragma unroll
    for (int p = 0; p < 2; p++) {
        uint2 r;
        r.x = packh(planeof(s0x, p), planeof(s0y, p));
        r.y = packh(planeof(s1x, p), planeof(s1y, p));
        g_bsplit[p][N][kt][l] = r;
    }
}

// ---------------------------------------------------------------------------
// main fused kernel: 3-term fp16 split GEMM + argmin + outputs
// grid 256 CTAs x 128 threads; CTA tile 128 rows x 128 cols/chunk;
// warp tile 64x64 (warps 2x2); no smem in mainloop.
// ---------------------------------------------------------------------------
__global__ __launch_bounds__(128, 2)
void vq_main(const float* __restrict__ centers, float* __restrict__ out) {
    const int tid = threadIdx.x;
    const int w = tid >> 5, l = tid & 31;
    const int g = l >> 2, t = l & 3;
    const int mw = w >> 1, nw = w & 1;
    const int blk = blockIdx.x;
    const int Mb = blk * 8 + mw * 4;          // global A-tile base (of 2048)

    float x2r[8];
#pragma unroll
    for (int mt = 0; mt < 4; mt++)
#pragma unroll
        for (int h = 0; h < 2; h++)
            x2r[mt * 2 + h] = g_x2[blk * 128 + mw * 64 + mt * 16 + h * 8 + g];

    float bv[8];
    int   bi[8];
#pragma unroll
    for (int s = 0; s < 8; s++) { bv[s] = INFINITY; bi[s] = 0; }

    const uint4* __restrict__ Abase = &g_asplit[0][0][0][0];
    const uint2* __restrict__ Bbase = &g_bsplit[0][0][0][0];

    for (int ch = 0; ch < NCHUNK; ch++) {
        const int Nb = ch * 16 + nw * 8;      // global B-tile base (of 800)
        float acc[4][8][4];
#pragma unroll
        for (int mt = 0; mt < 4; mt++)
#pragma unroll
            for (int nt = 0; nt < 8; nt++)
#pragma unroll
                for (int q = 0; q < 4; q++) acc[mt][nt][q] = 0.0f;

#pragma unroll 1
        for (int term = 0; term < 3; term++) {
            int sa = (term == 2) ? 1 : 0;     // aa, ab, ba
            int sb = (term == 1) ? 1 : 0;
            const uint4* Ap = Abase + ((size_t)(sa * AMT + Mb) * 8) * 32 + l;
            const uint2* Bp = Bbase + ((size_t)(sb * BNT + Nb) * 8) * 32 + l;
#pragma unroll
            for (int kt = 0; kt < 8; kt++) {
                uint4 a[4];
                uint2 b[8];
#pragma unroll
                for (int mt = 0; mt < 4; mt++) a[mt] = __ldg(Ap + (size_t)mt * 256 + kt * 32);
#pragma unroll
                for (int nt = 0; nt < 8; nt++) b[nt] = __ldg(Bp + (size_t)nt * 256 + kt * 32);
#pragma unroll
                for (int mt = 0; mt < 4; mt++)
#pragma unroll
                    for (int nt = 0; nt < 8; nt++)
                        mma16816(acc[mt][nt], a[mt], b[nt]);
            }
        }

        // fold into running argmin with reference rounding: (x2 + c2) - 2*dot
#pragma unroll
        for (int nt = 0; nt < 8; nt++) {
            int col0 = ch * 128 + nw * 64 + nt * 8 + 2 * t;
            float2 c2v = *reinterpret_cast<const float2*>(&g_c2[col0]);
#pragma unroll
            for (int mt = 0; mt < 4; mt++) {
                float t00 = x2r[mt * 2 + 0] + c2v.x;
                float t01 = x2r[mt * 2 + 0] + c2v.y;
                float t10 = x2r[mt * 2 + 1] + c2v.x;
                float t11 = x2r[mt * 2 + 1] + c2v.y;
                float s00 = t00 - 2.0f * acc[mt][nt][0];
                float s01 = t01 - 2.0f * acc[mt][nt][1];
                float s10 = t10 - 2.0f * acc[mt][nt][2];
                float s11 = t11 - 2.0f * acc[mt][nt][3];
                if (s00 < bv[mt * 2 + 0]) { bv[mt * 2 + 0] = s00; bi[mt * 2 + 0] = col0; }
                if (s01 < bv[mt * 2 + 0]) { bv[mt * 2 + 0] = s01; bi[mt * 2 + 0] = col0 + 1; }
                if (s10 < bv[mt * 2 + 1]) { bv[mt * 2 + 1] = s10; bi[mt * 2 + 1] = col0; }
                if (s11 < bv[mt * 2 + 1]) { bv[mt * 2 + 1] = s11; bi[mt * 2 + 1] = col0 + 1; }
            }
        }
    }

    // reduce across the 4 quad lanes (t = 0..3 share the same rows)
#pragma unroll
    for (int s = 0; s < 8; s++) {
#pragma unroll
        for (int off = 1; off <= 2; off <<= 1) {
            float ov = __shfl_xor_sync(0xFFFFFFFFu, bv[s], off);
            int   oi = __shfl_xor_sync(0xFFFFFFFFu, bi[s], off);
            if (ov < bv[s] || (ov == bv[s] && oi < bi[s])) { bv[s] = ov; bi[s] = oi; }
        }
    }

    // cross-warp (nw pair) reduction via smem
    __shared__ float srv[2][128];
    __shared__ int   sri[2][128];
    if (t == 0) {
#pragma unroll
        for (int s = 0; s < 8; s++) {
            int row = mw * 64 + (s >> 1) * 16 + (s & 1) * 8 + g;
            srv[nw][row] = bv[s];
            sri[nw][row] = bi[s];
        }
    }
    __syncthreads();

    if (tid < 128) {
        float v0 = srv[0][tid], v1 = srv[1][tid];
        int   i0 = sri[0][tid], i1 = sri[1][tid];
        float fv = v0; int fi = i0;
        if (v1 < v0 || (v1 == v0 && i1 < i0)) { fv = v1; fi = i1; }
        int gr = blk * 128 + tid;
        float* outAssign = out + (size_t)BATCH * DIM;
        float* outDist   = outAssign + BATCH;
        float* outClass  = outDist + BATCH;
        outAssign[gr] = (float)(fi % KC);
        outDist[gr]   = sqrtf(fmaxf(fv, 0.0f));
        outClass[gr]  = (float)(fi / KC);
        // gather quantized row = centers[fi]
        const float4* cg = reinterpret_cast<const float4*>(centers) + (size_t)fi * 32;
        float4* og = reinterpret_cast<float4*>(out) + (size_t)gr * 32;
#pragma unroll 8
        for (int q = 0; q < 32; q++) og[q] = cg[q];
    }
}

extern "C" void kernel_launch(void* const* d_in, const int* in_sizes, int n_in,
                              void* d_out, int out_size) {
    const float* x       = (const float*)d_in[0];
    const float* centers = (const float*)d_in[1];
    float* out = (float*)d_out;

    float* d_x2; cudaGetSymbolAddress((void**)&d_x2, g_x2);
    float* d_c2; cudaGetSymbolAddress((void**)&d_c2, g_c2);

    norm_kernel<<<(BATCH * 32 + 255) / 256, 256>>>(x, d_x2, BATCH);
    norm_kernel<<<(NCENT * 32 + 255) / 256, 256>>>(centers, d_c2, NCENT);
    prep_a_kernel<<<(AMT * 8 * 32) / 256, 256>>>(x);
    prep_b_kernel<<<(BNT * 8 * 32) / 256, 256>>>(centers);
    vq_main<<<BATCH / 128, 128>>>(centers, out);
}

// round 5
// speedup vs baseline: 4.0449x; 1.0541x over previous
#include <cuda_runtime.h>
#include <cuda_fp16.h>
#include <math.h>
#include <stdint.h>

// ---------------- problem constants ----------------
#define BATCH     32768
#define DIM       128
#define NCENT     6400
#define KC        64
#define AMT       (BATCH / 16)     // 2048 A row-tiles (m16)
#define BNT       (NCENT / 8)      // 800  B col-tiles (n8)
#define NCHUNK    50               // chunks of 128 centers

// ---------------- device scratch (fragment-layout fp16 split planes) -------
// A frag tile (m16 x k16): 32 lanes x uint4 (8 fp16)
// B frag PAIR tile (k32 x n8): 32 lanes x uint4 = {kt_even.b0,b1, kt_odd.b0,b1}
__device__ uint4 g_asplit[2][AMT][8][32];   // 16.8 MB
__device__ uint4 g_bsplit[2][BNT][4][32];   // 3.3 MB  (4 kt-pairs)
__device__ float g_c2[NCENT];
__device__ float g_x2[BATCH];

// ---------------- helpers ----------------
__device__ __forceinline__ uint32_t packh(float lo, float hi) {
    __half2 h = __floats2half2_rn(lo, hi);
    return *reinterpret_cast<uint32_t*>(&h);
}
struct Split2 { float a, b; };
__device__ __forceinline__ Split2 split2(float v) {
    Split2 s;
    s.a = __half2float(__float2half_rn(v));
    s.b = v - s.a;
    return s;
}
__device__ __forceinline__ float planeof(const Split2& s, int p) {
    return p == 0 ? s.a : s.b;
}

__device__ __forceinline__ void mma16816(float* d, const uint4& a,
                                         uint32_t b0, uint32_t b1) {
    asm volatile(
        "mma.sync.aligned.m16n8k16.row.col.f32.f16.f16.f32 "
        "{%0,%1,%2,%3}, {%4,%5,%6,%7}, {%8,%9}, {%0,%1,%2,%3};"
        : "+f"(d[0]), "+f"(d[1]), "+f"(d[2]), "+f"(d[3])
        : "r"(a.x), "r"(a.y), "r"(a.z), "r"(a.w), "r"(b0), "r"(b1));
}

// ---------------------------------------------------------------------------
// norms: one warp per vector
// ---------------------------------------------------------------------------
__global__ void norm_kernel(const float* __restrict__ v, float* __restrict__ out, int n) {
    int warp = (blockIdx.x * blockDim.x + threadIdx.x) >> 5;
    int lane = threadIdx.x & 31;
    if (warp >= n) return;
    float4 q = reinterpret_cast<const float4*>(v)[warp * (DIM / 4) + lane];
    float s = q.x * q.x + q.y * q.y + q.z * q.z + q.w * q.w;
#pragma unroll
    for (int off = 16; off > 0; off >>= 1)
        s += __shfl_xor_sync(0xFFFFFFFFu, s, off);
    if (lane == 0) out[warp] = s;
}

// ---------------------------------------------------------------------------
// prep A: x -> 2 fp16 planes in mma A-fragment layout
// ---------------------------------------------------------------------------
__global__ void prep_a_kernel(const float* __restrict__ x) {
    int idx = blockIdx.x * blockDim.x + threadIdx.x;   // 2048*8*32
    int M  = idx >> 8;
    int kt = (idx >> 5) & 7;
    int l  = idx & 31;
    int g = l >> 2, t = l & 3;
    int r0 = M * 16 + g, r1 = r0 + 8;
    int c0 = kt * 16 + 2 * t;
    float2 v00 = *reinterpret_cast<const float2*>(x + (size_t)r0 * DIM + c0);
    float2 v10 = *reinterpret_cast<const float2*>(x + (size_t)r1 * DIM + c0);
    float2 v02 = *reinterpret_cast<const float2*>(x + (size_t)r0 * DIM + c0 + 8);
    float2 v12 = *reinterpret_cast<const float2*>(x + (size_t)r1 * DIM + c0 + 8);
    Split2 s00x = split2(v00.x), s00y = split2(v00.y);
    Split2 s10x = split2(v10.x), s10y = split2(v10.y);
    Split2 s02x = split2(v02.x), s02y = split2(v02.y);
    Split2 s12x = split2(v12.x), s12y = split2(v12.y);
#pragma unroll
    for (int p = 0; p < 2; p++) {
        uint4 r;
        r.x = packh(planeof(s00x, p), planeof(s00y, p));
        r.y = packh(planeof(s10x, p), planeof(s10y, p));
        r.z = packh(planeof(s02x, p), planeof(s02y, p));
        r.w = packh(planeof(s12x, p), planeof(s12y, p));
        g_asplit[p][M][kt][l] = r;
    }
}

// ---------------------------------------------------------------------------
// prep B: centers -> 2 fp16 planes, B-fragment layout, kt-PAIR packed uint4
// thread = (Ntile, kt2, lane); handles kt = 2*kt2 and 2*kt2+1
// ---------------------------------------------------------------------------
__global__ void prep_b_kernel(const float* __restrict__ centers) {
    int idx = blockIdx.x * blockDim.x + threadIdx.x;   // 800*4*32
    int N   = idx >> 7;
    int kt2 = (idx >> 5) & 3;
    int l   = idx & 31;
    int g = l >> 2, t = l & 3;
    int n = N * 8 + g;
    const float* row = centers + (size_t)n * DIM;
    int c0 = kt2 * 32 + 2 * t;                  // even kt base col
    float2 e0 = *reinterpret_cast<const float2*>(row + c0);
    float2 e1 = *reinterpret_cast<const float2*>(row + c0 + 8);
    float2 o0 = *reinterpret_cast<const float2*>(row + c0 + 16);
    float2 o1 = *reinterpret_cast<const float2*>(row + c0 + 24);
    Split2 se0x = split2(e0.x), se0y = split2(e0.y);
    Split2 se1x = split2(e1.x), se1y = split2(e1.y);
    Split2 so0x = split2(o0.x), so0y = split2(o0.y);
    Split2 so1x = split2(o1.x), so1y = split2(o1.y);
#pragma unroll
    for (int p = 0; p < 2; p++) {
        uint4 r;
        r.x = packh(planeof(se0x, p), planeof(se0y, p));   // even kt b0
        r.y = packh(planeof(se1x, p), planeof(se1y, p));   // even kt b1
        r.z = packh(planeof(so0x, p), planeof(so0y, p));   // odd  kt b0
        r.w = packh(planeof(so1x, p), planeof(so1y, p));   // odd  kt b1
        g_bsplit[p][N][kt2][l] = r;
    }
}

// ---------------------------------------------------------------------------
// main fused kernel: 3-term fp16 split GEMM + argmin + outputs
// grid 256 CTAs x 128 threads; warp tile 64x64 (warps 2x2); no mainloop smem.
// ---------------------------------------------------------------------------
__global__ __launch_bounds__(128, 2)
void vq_main(const float* __restrict__ centers, float* __restrict__ out) {
    const int tid = threadIdx.x;
    const int w = tid >> 5, l = tid & 31;
    const int g = l >> 2, t = l & 3;
    const int mw = w >> 1, nw = w & 1;
    const int blk = blockIdx.x;
    const int Mb = blk * 8 + mw * 4;          // global A-tile base (of 2048)

    float x2r[8];
#pragma unroll
    for (int mt = 0; mt < 4; mt++)
#pragma unroll
        for (int h = 0; h < 2; h++)
            x2r[mt * 2 + h] = g_x2[blk * 128 + mw * 64 + mt * 16 + h * 8 + g];

    float bv[8];
    int   bi[8];
#pragma unroll
    for (int s = 0; s < 8; s++) { bv[s] = INFINITY; bi[s] = 0; }

    const uint4* __restrict__ Abase = &g_asplit[0][0][0][0];
    const uint4* __restrict__ Bbase = &g_bsplit[0][0][0][0];

    for (int ch = 0; ch < NCHUNK; ch++) {
        const int Nb = ch * 16 + nw * 8;      // global B-tile base (of 800)
        float acc[4][8][4];
#pragma unroll
        for (int mt = 0; mt < 4; mt++)
#pragma unroll
            for (int nt = 0; nt < 8; nt++)
#pragma unroll
                for (int q = 0; q < 4; q++) acc[mt][nt][q] = 0.0f;

#pragma unroll 1
        for (int term = 0; term < 3; term++) {
            int sa = (term == 2) ? 1 : 0;     // aa, ab, ba
            int sb = (term == 1) ? 1 : 0;
            const uint4* Ap = Abase + ((size_t)(sa * AMT + Mb) * 8) * 32 + l;
            const uint4* Bp = Bbase + ((size_t)(sb * BNT + Nb) * 4) * 32 + l;
#pragma unroll
            for (int kt2 = 0; kt2 < 4; kt2++) {
                uint4 b4[8];
#pragma unroll
                for (int nt = 0; nt < 8; nt++) b4[nt] = __ldg(Bp + (size_t)nt * 128 + kt2 * 32);
                uint4 a0[4];
#pragma unroll
                for (int mt = 0; mt < 4; mt++) a0[mt] = __ldg(Ap + (size_t)mt * 256 + (2 * kt2) * 32);
#pragma unroll
                for (int mt = 0; mt < 4; mt++)
#pragma unroll
                    for (int nt = 0; nt < 8; nt++)
                        mma16816(acc[mt][nt], a0[mt], b4[nt].x, b4[nt].y);
                uint4 a1[4];
#pragma unroll
                for (int mt = 0; mt < 4; mt++) a1[mt] = __ldg(Ap + (size_t)mt * 256 + (2 * kt2 + 1) * 32);
#pragma unroll
                for (int mt = 0; mt < 4; mt++)
#pragma unroll
                    for (int nt = 0; nt < 8; nt++)
                        mma16816(acc[mt][nt], a1[mt], b4[nt].z, b4[nt].w);
            }
        }

        // fold into running argmin with reference rounding: (x2 + c2) - 2*dot
#pragma unroll
        for (int nt = 0; nt < 8; nt++) {
            int col0 = ch * 128 + nw * 64 + nt * 8 + 2 * t;
            float2 c2v = *reinterpret_cast<const float2*>(&g_c2[col0]);
#pragma unroll
            for (int mt = 0; mt < 4; mt++) {
                float t00 = x2r[mt * 2 + 0] + c2v.x;
                float t01 = x2r[mt * 2 + 0] + c2v.y;
                float t10 = x2r[mt * 2 + 1] + c2v.x;
                float t11 = x2r[mt * 2 + 1] + c2v.y;
                float s00 = t00 - 2.0f * acc[mt][nt][0];
                float s01 = t01 - 2.0f * acc[mt][nt][1];
                float s10 = t10 - 2.0f * acc[mt][nt][2];
                float s11 = t11 - 2.0f * acc[mt][nt][3];
                if (s00 < bv[mt * 2 + 0]) { bv[mt * 2 + 0] = s00; bi[mt * 2 + 0] = col0; }
                if (s01 < bv[mt * 2 + 0]) { bv[mt * 2 + 0] = s01; bi[mt * 2 + 0] = col0 + 1; }
                if (s10 < bv[mt * 2 + 1]) { bv[mt * 2 + 1] = s10; bi[mt * 2 + 1] = col0; }
                if (s11 < bv[mt * 2 + 1]) { bv[mt * 2 + 1] = s11; bi[mt * 2 + 1] = col0 + 1; }
            }
        }
    }

    // reduce across the 4 quad lanes (t = 0..3 share the same rows)
#pragma unroll
    for (int s = 0; s < 8; s++) {
#pragma unroll
        for (int off = 1; off <= 2; off <<= 1) {
            float ov = __shfl_xor_sync(0xFFFFFFFFu, bv[s], off);
            int   oi = __shfl_xor_sync(0xFFFFFFFFu, bi[s], off);
            if (ov < bv[s] || (ov == bv[s] && oi < bi[s])) { bv[s] = ov; bi[s] = oi; }
        }
    }

    // cross-warp (nw pair) reduction via smem
    __shared__ float srv[2][128];
    __shared__ int   sri[2][128];
    if (t == 0) {
#pragma unroll
        for (int s = 0; s < 8; s++) {
            int row = mw * 64 + (s >> 1) * 16 + (s & 1) * 8 + g;
            srv[nw][row] = bv[s];
            sri[nw][row] = bi[s];
        }
    }
    __syncthreads();

    if (tid < 128) {
        float v0 = srv[0][tid], v1 = srv[1][tid];
        int   i0 = sri[0][tid], i1 = sri[1][tid];
        float fv = v0; int fi = i0;
        if (v1 < v0 || (v1 == v0 && i1 < i0)) { fv = v1; fi = i1; }
        int gr = blk * 128 + tid;
        float* outAssign = out + (size_t)BATCH * DIM;
        float* outDist   = outAssign + BATCH;
        float* outClass  = outDist + BATCH;
        outAssign[gr] = (float)(fi % KC);
        outDist[gr]   = sqrtf(fmaxf(fv, 0.0f));
        outClass[gr]  = (float)(fi / KC);
        // gather quantized row = centers[fi]
        const float4* cg = reinterpret_cast<const float4*>(centers) + (size_t)fi * 32;
        float4* og = reinterpret_cast<float4*>(out) + (size_t)gr * 32;
#pragma unroll 8
        for (int q = 0; q < 32; q++) og[q] = cg[q];
    }
}

extern "C" void kernel_launch(void* const* d_in, const int* in_sizes, int n_in,
                              void* d_out, int out_size) {
    const float* x       = (const float*)d_in[0];
    const float* centers = (const float*)d_in[1];
    float* out = (float*)d_out;

    float* d_x2; cudaGetSymbolAddress((void**)&d_x2, g_x2);
    float* d_c2; cudaGetSymbolAddress((void**)&d_c2, g_c2);

    norm_kernel<<<(BATCH * 32 + 255) / 256, 256>>>(x, d_x2, BATCH);
    norm_kernel<<<(NCENT * 32 + 255) / 256, 256>>>(centers, d_c2, NCENT);
    prep_a_kernel<<<(AMT * 8 * 32) / 256, 256>>>(x);
    prep_b_kernel<<<(BNT * 4 * 32) / 256, 256>>>(centers);
    vq_main<<<BATCH / 128, 128>>>(centers, out);
}

// round 6
// speedup vs baseline: 4.0636x; 1.0046x over previous
#include <cuda_runtime.h>
#include <cuda_fp16.h>
#include <math.h>
#include <stdint.h>

// ---------------- problem constants ----------------
#define BATCH     32768
#define DIM       128
#define NCENT     6400
#define KC        64
#define AMT       (BATCH / 16)     // 2048 A row-tiles (m16)
#define BNT       (NCENT / 8)      // 800  B col-tiles (n8)
#define NUNITS    2048             // (32768/64 row-units) x 4 N-slices
#define NSLC_T    200              // n8-tiles per N-slice (1600 centers)
#define VQ_GRID   296              // 148 SMs x occ 2

// ---------------- device scratch ----------------
__device__ uint4 g_asplit[2][AMT][8][32];            // 16.8 MB
__device__ uint4 g_bsplit[2][BNT][4][32];            // 3.3 MB (kt-pair packed)
__device__ float g_c2[NCENT];
__device__ float g_x2[BATCH];
__device__ unsigned long long g_best[BATCH];         // packed (enc(sq)<<32 | idx)
__device__ int   g_ticket;

// ---------------- helpers ----------------
__device__ __forceinline__ uint32_t packh(float lo, float hi) {
    __half2 h = __floats2half2_rn(lo, hi);
    return *reinterpret_cast<uint32_t*>(&h);
}
struct Split2 { float a, b; };
__device__ __forceinline__ Split2 split2(float v) {
    Split2 s;
    s.a = __half2float(__float2half_rn(v));
    s.b = v - s.a;
    return s;
}
__device__ __forceinline__ float planeof(const Split2& s, int p) {
    return p == 0 ? s.a : s.b;
}
// monotone float->u32 encoding (preserves < ordering)
__device__ __forceinline__ uint32_t encf(float f) {
    uint32_t u = __float_as_uint(f);
    return (u & 0x80000000u) ? ~u : (u | 0x80000000u);
}
__device__ __forceinline__ float decf(uint32_t e) {
    uint32_t u = (e & 0x80000000u) ? (e ^ 0x80000000u) : ~e;
    return __uint_as_float(u);
}

__device__ __forceinline__ void mma16816(float* d, const uint4& a,
                                         uint32_t b0, uint32_t b1) {
    asm volatile(
        "mma.sync.aligned.m16n8k16.row.col.f32.f16.f16.f32 "
        "{%0,%1,%2,%3}, {%4,%5,%6,%7}, {%8,%9}, {%0,%1,%2,%3};"
        : "+f"(d[0]), "+f"(d[1]), "+f"(d[2]), "+f"(d[3])
        : "r"(a.x), "r"(a.y), "r"(a.z), "r"(a.w), "r"(b0), "r"(b1));
}

// ---------------------------------------------------------------------------
// norms: one warp per vector
// ---------------------------------------------------------------------------
__global__ void norm_kernel(const float* __restrict__ v, float* __restrict__ out, int n) {
    int warp = (blockIdx.x * blockDim.x + threadIdx.x) >> 5;
    int lane = threadIdx.x & 31;
    if (warp >= n) return;
    float4 q = reinterpret_cast<const float4*>(v)[warp * (DIM / 4) + lane];
    float s = q.x * q.x + q.y * q.y + q.z * q.z + q.w * q.w;
#pragma unroll
    for (int off = 16; off > 0; off >>= 1)
        s += __shfl_xor_sync(0xFFFFFFFFu, s, off);
    if (lane == 0) out[warp] = s;
}

// ---------------------------------------------------------------------------
// prep A: x -> 2 fp16 planes in mma A-fragment layout
// ---------------------------------------------------------------------------
__global__ void prep_a_kernel(const float* __restrict__ x) {
    int idx = blockIdx.x * blockDim.x + threadIdx.x;   // 2048*8*32
    int M  = idx >> 8;
    int kt = (idx >> 5) & 7;
    int l  = idx & 31;
    int g = l >> 2, t = l & 3;
    int r0 = M * 16 + g, r1 = r0 + 8;
    int c0 = kt * 16 + 2 * t;
    float2 v00 = *reinterpret_cast<const float2*>(x + (size_t)r0 * DIM + c0);
    float2 v10 = *reinterpret_cast<const float2*>(x + (size_t)r1 * DIM + c0);
    float2 v02 = *reinterpret_cast<const float2*>(x + (size_t)r0 * DIM + c0 + 8);
    float2 v12 = *reinterpret_cast<const float2*>(x + (size_t)r1 * DIM + c0 + 8);
    Split2 s00x = split2(v00.x), s00y = split2(v00.y);
    Split2 s10x = split2(v10.x), s10y = split2(v10.y);
    Split2 s02x = split2(v02.x), s02y = split2(v02.y);
    Split2 s12x = split2(v12.x), s12y = split2(v12.y);
#pragma unroll
    for (int p = 0; p < 2; p++) {
        uint4 r;
        r.x = packh(planeof(s00x, p), planeof(s00y, p));
        r.y = packh(planeof(s10x, p), planeof(s10y, p));
        r.z = packh(planeof(s02x, p), planeof(s02y, p));
        r.w = packh(planeof(s12x, p), planeof(s12y, p));
        g_asplit[p][M][kt][l] = r;
    }
}

// ---------------------------------------------------------------------------
// prep B: centers -> 2 fp16 planes, B-fragment layout, kt-pair packed uint4
// ---------------------------------------------------------------------------
__global__ void prep_b_kernel(const float* __restrict__ centers) {
    int idx = blockIdx.x * blockDim.x + threadIdx.x;   // 800*4*32
    int N   = idx >> 7;
    int kt2 = (idx >> 5) & 3;
    int l   = idx & 31;
    int g = l >> 2, t = l & 3;
    int n = N * 8 + g;
    const float* row = centers + (size_t)n * DIM;
    int c0 = kt2 * 32 + 2 * t;
    float2 e0 = *reinterpret_cast<const float2*>(row + c0);
    float2 e1 = *reinterpret_cast<const float2*>(row + c0 + 8);
    float2 o0 = *reinterpret_cast<const float2*>(row + c0 + 16);
    float2 o1 = *reinterpret_cast<const float2*>(row + c0 + 24);
    Split2 se0x = split2(e0.x), se0y = split2(e0.y);
    Split2 se1x = split2(e1.x), se1y = split2(e1.y);
    Split2 so0x = split2(o0.x), so0y = split2(o0.y);
    Split2 so1x = split2(o1.x), so1y = split2(o1.y);
#pragma unroll
    for (int p = 0; p < 2; p++) {
        uint4 r;
        r.x = packh(planeof(se0x, p), planeof(se0y, p));
        r.y = packh(planeof(se1x, p), planeof(se1y, p));
        r.z = packh(planeof(so0x, p), planeof(so0y, p));
        r.w = packh(planeof(so1x, p), planeof(so1y, p));
        g_bsplit[p][N][kt2][l] = r;
    }
}

// ---------------------------------------------------------------------------
// init: reset ticket and per-row best keys (runs every replay)
// ---------------------------------------------------------------------------
__global__ void init_kernel() {
    int i = blockIdx.x * blockDim.x + threadIdx.x;
    if (i == 0) g_ticket = 0;
    if (i < BATCH) g_best[i] = 0xFFFFFFFFFFFFFFFFull;
}

// ---------------------------------------------------------------------------
// one chunk of NT n8-tiles per warp (NT = 8 full chunk / 4 tail chunk)
// ---------------------------------------------------------------------------
template<int NT>
__device__ __forceinline__ void do_chunk(
    const uint4* __restrict__ Abase, const uint4* __restrict__ Bbase,
    int mtb, int tile0w, const float* x2r, float* bv, int* bi, int l, int t)
{
    float acc[2][NT][4];
#pragma unroll
    for (int mt = 0; mt < 2; mt++)
#pragma unroll
        for (int nt = 0; nt < NT; nt++)
#pragma unroll
            for (int q = 0; q < 4; q++) acc[mt][nt][q] = 0.0f;

#pragma unroll 1
    for (int term = 0; term < 3; term++) {
        int sa = (term == 2) ? 1 : 0;     // aa, ab, ba
        int sb = (term == 1) ? 1 : 0;
        const uint4* Ap = Abase + ((size_t)(sa * AMT + mtb)) * 256 + l;
        const uint4* Bp = Bbase + ((size_t)(sb * BNT + tile0w)) * 128 + l;
#pragma unroll
        for (int kt2 = 0; kt2 < 4; kt2++) {
            uint4 b4[NT];
#pragma unroll
            for (int nt = 0; nt < NT; nt++) b4[nt] = __ldg(Bp + (size_t)nt * 128 + kt2 * 32);
            uint4 a0[2], a1[2];
#pragma unroll
            for (int mt = 0; mt < 2; mt++) a0[mt] = __ldg(Ap + (size_t)mt * 256 + (2 * kt2) * 32);
#pragma unroll
            for (int mt = 0; mt < 2; mt++) a1[mt] = __ldg(Ap + (size_t)mt * 256 + (2 * kt2 + 1) * 32);
#pragma unroll
            for (int mt = 0; mt < 2; mt++)
#pragma unroll
                for (int nt = 0; nt < NT; nt++)
                    mma16816(acc[mt][nt], a0[mt], b4[nt].x, b4[nt].y);
#pragma unroll
            for (int mt = 0; mt < 2; mt++)
#pragma unroll
                for (int nt = 0; nt < NT; nt++)
                    mma16816(acc[mt][nt], a1[mt], b4[nt].z, b4[nt].w);
        }
    }

    // fold: sq = (x2 + c2) - 2*dot  (reference rounding order)
#pragma unroll
    for (int nt = 0; nt < NT; nt++) {
        int col0 = (tile0w + nt) * 8 + 2 * t;
        float2 c2v = *reinterpret_cast<const float2*>(&g_c2[col0]);
#pragma unroll
        for (int mt = 0; mt < 2; mt++) {
            float t00 = x2r[mt * 2 + 0] + c2v.x;
            float t01 = x2r[mt * 2 + 0] + c2v.y;
            float t10 = x2r[mt * 2 + 1] + c2v.x;
            float t11 = x2r[mt * 2 + 1] + c2v.y;
            float s00 = t00 - 2.0f * acc[mt][nt][0];
            float s01 = t01 - 2.0f * acc[mt][nt][1];
            float s10 = t10 - 2.0f * acc[mt][nt][2];
            float s11 = t11 - 2.0f * acc[mt][nt][3];
            if (s00 < bv[mt * 2 + 0]) { bv[mt * 2 + 0] = s00; bi[mt * 2 + 0] = col0; }
            if (s01 < bv[mt * 2 + 0]) { bv[mt * 2 + 0] = s01; bi[mt * 2 + 0] = col0 + 1; }
            if (s10 < bv[mt * 2 + 1]) { bv[mt * 2 + 1] = s10; bi[mt * 2 + 1] = col0; }
            if (s11 < bv[mt * 2 + 1]) { bv[mt * 2 + 1] = s11; bi[mt * 2 + 1] = col0 + 1; }
        }
    }
}

// ---------------------------------------------------------------------------
// main: persistent CTAs pull (64-row x 1600-center) units via atomic ticket
// ---------------------------------------------------------------------------
__global__ __launch_bounds__(128, 2)
void vq_main() {
    const int tid = threadIdx.x;
    const int w = tid >> 5, l = tid & 31;
    const int g = l >> 2, t = l & 3;
    const int mw = w >> 1, nw = w & 1;

    const uint4* __restrict__ Abase = &g_asplit[0][0][0][0];
    const uint4* __restrict__ Bbase = &g_bsplit[0][0][0][0];

    __shared__ int s_u;
    for (;;) {
        __syncthreads();
        if (tid == 0) s_u = atomicAdd(&g_ticket, 1);
        __syncthreads();
        int u = s_u;
        if (u >= NUNITS) break;

        const int um = u >> 2;            // 64-row block index (0..511)
        const int s  = u & 3;             // N-slice
        const int r0 = um * 64;
        const int mtb = um * 4 + mw * 2;  // first global m16-tile for this warp

        float x2r[4];
#pragma unroll
        for (int mt = 0; mt < 2; mt++)
#pragma unroll
            for (int h = 0; h < 2; h++)
                x2r[mt * 2 + h] = g_x2[r0 + mw * 32 + mt * 16 + h * 8 + g];

        float bv[4];
        int   bi[4];
#pragma unroll
        for (int q = 0; q < 4; q++) { bv[q] = INFINITY; bi[q] = 0; }

        const int tbase = s * NSLC_T;
#pragma unroll 1
        for (int ch = 0; ch < 12; ch++)
            do_chunk<8>(Abase, Bbase, mtb, tbase + ch * 16 + nw * 8, x2r, bv, bi, l, t);
        do_chunk<4>(Abase, Bbase, mtb, tbase + 192 + nw * 4, x2r, bv, bi, l, t);

        // reduce across quad lanes (t)
#pragma unroll
        for (int q = 0; q < 4; q++) {
#pragma unroll
            for (int off = 1; off <= 2; off <<= 1) {
                float ov = __shfl_xor_sync(0xFFFFFFFFu, bv[q], off);
                int   oi = __shfl_xor_sync(0xFFFFFFFFu, bi[q], off);
                if (ov < bv[q] || (ov == bv[q] && oi < bi[q])) { bv[q] = ov; bi[q] = oi; }
            }
        }
        if (t == 0) {
#pragma unroll
            for (int q = 0; q < 4; q++) {
                int row = r0 + mw * 32 + (q >> 1) * 16 + (q & 1) * 8 + g;
                unsigned long long key =
                    ((unsigned long long)encf(bv[q]) << 32) | (unsigned long long)(uint32_t)bi[q];
                atomicMin(&g_best[row], key);
            }
        }
    }
}

// ---------------------------------------------------------------------------
// final: decode best key per row, write scalars + gather quantized row
// one warp per row
// ---------------------------------------------------------------------------
__global__ void final_kernel(const float* __restrict__ centers, float* __restrict__ out) {
    int warp = (blockIdx.x * blockDim.x + threadIdx.x) >> 5;
    int lane = threadIdx.x & 31;
    if (warp >= BATCH) return;
    unsigned long long key = g_best[warp];
    int fi = (int)(uint32_t)(key & 0xFFFFFFFFull);
    float sq = decf((uint32_t)(key >> 32));
    if (lane == 0) {
        float* outAssign = out + (size_t)BATCH * DIM;
        float* outDist   = outAssign + BATCH;
        float* outClass  = outDist + BATCH;
        outAssign[warp] = (float)(fi % KC);
        outDist[warp]   = sqrtf(fmaxf(sq, 0.0f));
        outClass[warp]  = (float)(fi / KC);
    }
    float4 v = reinterpret_cast<const float4*>(centers)[(size_t)fi * 32 + lane];
    reinterpret_cast<float4*>(out)[(size_t)warp * 32 + lane] = v;
}

extern "C" void kernel_launch(void* const* d_in, const int* in_sizes, int n_in,
                              void* d_out, int out_size) {
    const float* x       = (const float*)d_in[0];
    const float* centers = (const float*)d_in[1];
    float* out = (float*)d_out;

    float* d_x2; cudaGetSymbolAddress((void**)&d_x2, g_x2);
    float* d_c2; cudaGetSymbolAddress((void**)&d_c2, g_c2);

    norm_kernel<<<(BATCH * 32 + 255) / 256, 256>>>(x, d_x2, BATCH);
    norm_kernel<<<(NCENT * 32 + 255) / 256, 256>>>(centers, d_c2, NCENT);
    prep_a_kernel<<<(AMT * 8 * 32) / 256, 256>>>(x);
    prep_b_kernel<<<(BNT * 4 * 32) / 256, 256>>>(centers);
    init_kernel<<<(BATCH + 255) / 256, 256>>>();
    vq_main<<<VQ_GRID, 128>>>();
    final_kernel<<<(BATCH * 32 + 255) / 256, 256>>>(centers, out);
}

// round 7
// speedup vs baseline: 4.4932x; 1.1057x over previous
#include <cuda_runtime.h>
#include <cuda_fp16.h>
#include <math.h>
#include <stdint.h>

// ---------------- problem constants ----------------
#define BATCH     32768
#define DIM       128
#define NCENT     6400
#define KC        64
#define AMT       (BATCH / 16)     // 2048 A row-tiles (m16)
#define BNT       (NCENT / 8)      // 800  B col-tiles (n8)
#define NSLICES   8
#define NSLC_T    100              // n8-tiles per N-slice (800 centers)
#define NUNITS    (512 * NSLICES)  // 512 row-blocks x 8 slices = 4096
#define VQ_GRID   444              // 148 SMs x occ 3

// ---------------- device scratch ----------------
__device__ uint4 g_asplit[2][AMT][8][32];            // 16.8 MB
__device__ uint4 g_bsplit[2][BNT][4][32];            // 3.3 MB (kt-pair packed)
__device__ float g_c2[NCENT];
__device__ float g_x2[BATCH];
__device__ unsigned long long g_best[BATCH];         // packed (enc(sq)<<32 | idx)
__device__ int   g_ticket;

// ---------------- helpers ----------------
__device__ __forceinline__ uint32_t packh(float lo, float hi) {
    __half2 h = __floats2half2_rn(lo, hi);
    return *reinterpret_cast<uint32_t*>(&h);
}
struct Split2 { float a, b; };
__device__ __forceinline__ Split2 split2(float v) {
    Split2 s;
    s.a = __half2float(__float2half_rn(v));
    s.b = v - s.a;
    return s;
}
__device__ __forceinline__ float planeof(const Split2& s, int p) {
    return p == 0 ? s.a : s.b;
}
// monotone float->u32 encoding (preserves < ordering)
__device__ __forceinline__ uint32_t encf(float f) {
    uint32_t u = __float_as_uint(f);
    return (u & 0x80000000u) ? ~u : (u | 0x80000000u);
}
__device__ __forceinline__ float decf(uint32_t e) {
    uint32_t u = (e & 0x80000000u) ? (e ^ 0x80000000u) : ~e;
    return __uint_as_float(u);
}

__device__ __forceinline__ void mma16816(float* d, const uint4& a,
                                         uint32_t b0, uint32_t b1) {
    asm volatile(
        "mma.sync.aligned.m16n8k16.row.col.f32.f16.f16.f32 "
        "{%0,%1,%2,%3}, {%4,%5,%6,%7}, {%8,%9}, {%0,%1,%2,%3};"
        : "+f"(d[0]), "+f"(d[1]), "+f"(d[2]), "+f"(d[3])
        : "r"(a.x), "r"(a.y), "r"(a.z), "r"(a.w), "r"(b0), "r"(b1));
}

// ---------------------------------------------------------------------------
// fused prep A: one warp per x-row -> x2, A fragments (both planes),
// g_best reset, ticket reset.
// ---------------------------------------------------------------------------
__global__ void prep_ax_kernel(const float* __restrict__ x) {
    int warp = (blockIdx.x * blockDim.x + threadIdx.x) >> 5;
    int lane = threadIdx.x & 31;
    if (warp >= BATCH) return;
    int r = warp;
    int M = r >> 4, g = r & 15;
    int kt = lane >> 2, t = lane & 3;
    const float* row = x + (size_t)r * DIM;
    float2 lo = *reinterpret_cast<const float2*>(row + kt * 16 + 2 * t);
    float2 hi = *reinterpret_cast<const float2*>(row + kt * 16 + 8 + 2 * t);

    float s = lo.x * lo.x + lo.y * lo.y + hi.x * hi.x + hi.y * hi.y;
#pragma unroll
    for (int off = 16; off > 0; off >>= 1)
        s += __shfl_xor_sync(0xFFFFFFFFu, s, off);
    if (lane == 0) { g_x2[r] = s; g_best[r] = 0xFFFFFFFFFFFFFFFFull; }
    if (warp == 0 && lane == 1) g_ticket = 0;

    Split2 slx = split2(lo.x), sly = split2(lo.y);
    Split2 shx = split2(hi.x), shy = split2(hi.y);
    int fl = (g & 7) * 4 + t;   // fragment lane
#pragma unroll
    for (int p = 0; p < 2; p++) {
        uint32_t w0 = packh(planeof(slx, p), planeof(sly, p));
        uint32_t w1 = packh(planeof(shx, p), planeof(shy, p));
        uint32_t* base = reinterpret_cast<uint32_t*>(&g_asplit[p][M][kt][fl]);
        if (g < 8) { base[0] = w0; base[2] = w1; }   // .x, .z
        else       { base[1] = w0; base[3] = w1; }   // .y, .w
    }
}

// ---------------------------------------------------------------------------
// fused prep B: one warp per center row -> c2 + B fragments (kt-pair packed)
// lanes 0-15: plane 0, lanes 16-31: plane 1 (same data re-read, L1 hit)
// ---------------------------------------------------------------------------
__global__ void prep_bc_kernel(const float* __restrict__ centers) {
    int warp = (blockIdx.x * blockDim.x + threadIdx.x) >> 5;
    int lane = threadIdx.x & 31;
    if (warp >= NCENT) return;
    int n = warp;
    int N = n >> 3, g = n & 7;
    int p = lane >> 4, j = lane & 15;
    int kt2 = j >> 2, t = j & 3;
    const float* row = centers + (size_t)n * DIM;
    int c0 = kt2 * 32 + 2 * t;
    float2 e0 = *reinterpret_cast<const float2*>(row + c0);
    float2 e1 = *reinterpret_cast<const float2*>(row + c0 + 8);
    float2 o0 = *reinterpret_cast<const float2*>(row + c0 + 16);
    float2 o1 = *reinterpret_cast<const float2*>(row + c0 + 24);

    float s = (p == 0)
        ? (e0.x * e0.x + e0.y * e0.y + e1.x * e1.x + e1.y * e1.y +
           o0.x * o0.x + o0.y * o0.y + o1.x * o1.x + o1.y * o1.y)
        : 0.0f;
#pragma unroll
    for (int off = 16; off > 0; off >>= 1)
        s += __shfl_xor_sync(0xFFFFFFFFu, s, off);
    if (lane == 0) g_c2[n] = s;

    Split2 se0x = split2(e0.x), se0y = split2(e0.y);
    Split2 se1x = split2(e1.x), se1y = split2(e1.y);
    Split2 so0x = split2(o0.x), so0y = split2(o0.y);
    Split2 so1x = split2(o1.x), so1y = split2(o1.y);
    uint4 w;
    w.x = packh(planeof(se0x, p), planeof(se0y, p));
    w.y = packh(planeof(se1x, p), planeof(se1y, p));
    w.z = packh(planeof(so0x, p), planeof(so0y, p));
    w.w = packh(planeof(so1x, p), planeof(so1y, p));
    g_bsplit[p][N][kt2][g * 4 + t] = w;
}

// ---------------------------------------------------------------------------
// one chunk of NT n8-tiles per warp
// ---------------------------------------------------------------------------
template<int NT>
__device__ __forceinline__ void do_chunk(
    const uint4* __restrict__ Abase, const uint4* __restrict__ Bbase,
    int mtb, int tile0w, const float* x2r, float* bv, int* bi, int l, int t)
{
    float acc[2][NT][4];
#pragma unroll
    for (int mt = 0; mt < 2; mt++)
#pragma unroll
        for (int nt = 0; nt < NT; nt++)
#pragma unroll
            for (int q = 0; q < 4; q++) acc[mt][nt][q] = 0.0f;

#pragma unroll 1
    for (int term = 0; term < 3; term++) {
        int sa = (term == 2) ? 1 : 0;     // aa, ab, ba
        int sb = (term == 1) ? 1 : 0;
        const uint4* Ap = Abase + ((size_t)(sa * AMT + mtb)) * 256 + l;
        const uint4* Bp = Bbase + ((size_t)(sb * BNT + tile0w)) * 128 + l;
#pragma unroll
        for (int kt2 = 0; kt2 < 4; kt2++) {
            uint4 b4[NT];
#pragma unroll
            for (int nt = 0; nt < NT; nt++) b4[nt] = __ldg(Bp + (size_t)nt * 128 + kt2 * 32);
            uint4 a0[2], a1[2];
#pragma unroll
            for (int mt = 0; mt < 2; mt++) a0[mt] = __ldg(Ap + (size_t)mt * 256 + (2 * kt2) * 32);
#pragma unroll
            for (int mt = 0; mt < 2; mt++) a1[mt] = __ldg(Ap + (size_t)mt * 256 + (2 * kt2 + 1) * 32);
#pragma unroll
            for (int mt = 0; mt < 2; mt++)
#pragma unroll
                for (int nt = 0; nt < NT; nt++)
                    mma16816(acc[mt][nt], a0[mt], b4[nt].x, b4[nt].y);
#pragma unroll
            for (int mt = 0; mt < 2; mt++)
#pragma unroll
                for (int nt = 0; nt < NT; nt++)
                    mma16816(acc[mt][nt], a1[mt], b4[nt].z, b4[nt].w);
        }
    }

    // fold: sq = (x2 + c2) - 2*dot  (reference rounding order)
#pragma unroll
    for (int nt = 0; nt < NT; nt++) {
        int col0 = (tile0w + nt) * 8 + 2 * t;
        float2 c2v = *reinterpret_cast<const float2*>(&g_c2[col0]);
#pragma unroll
        for (int mt = 0; mt < 2; mt++) {
            float t00 = x2r[mt * 2 + 0] + c2v.x;
            float t01 = x2r[mt * 2 + 0] + c2v.y;
            float t10 = x2r[mt * 2 + 1] + c2v.x;
            float t11 = x2r[mt * 2 + 1] + c2v.y;
            float s00 = t00 - 2.0f * acc[mt][nt][0];
            float s01 = t01 - 2.0f * acc[mt][nt][1];
            float s10 = t10 - 2.0f * acc[mt][nt][2];
            float s11 = t11 - 2.0f * acc[mt][nt][3];
            if (s00 < bv[mt * 2 + 0]) { bv[mt * 2 + 0] = s00; bi[mt * 2 + 0] = col0; }
            if (s01 < bv[mt * 2 + 0]) { bv[mt * 2 + 0] = s01; bi[mt * 2 + 0] = col0 + 1; }
            if (s10 < bv[mt * 2 + 1]) { bv[mt * 2 + 1] = s10; bi[mt * 2 + 1] = col0; }
            if (s11 < bv[mt * 2 + 1]) { bv[mt * 2 + 1] = s11; bi[mt * 2 + 1] = col0 + 1; }
        }
    }
}

// ---------------------------------------------------------------------------
// main: persistent CTAs (occ 3) pull (64-row x 800-center) units.
// Ticket order: all CTAs sweep the SAME B slice concurrently (L2-hot).
// ---------------------------------------------------------------------------
__global__ __launch_bounds__(128, 3)
void vq_main() {
    const int tid = threadIdx.x;
    const int w = tid >> 5, l = tid & 31;
    const int g = l >> 2, t = l & 3;
    const int mw = w >> 1, nw = w & 1;

    const uint4* __restrict__ Abase = &g_asplit[0][0][0][0];
    const uint4* __restrict__ Bbase = &g_bsplit[0][0][0][0];

    __shared__ int s_u;
    for (;;) {
        __syncthreads();
        if (tid == 0) s_u = atomicAdd(&g_ticket, 1);
        __syncthreads();
        int u = s_u;
        if (u >= NUNITS) break;

        const int um = u & 511;           // 64-row block index
        const int s  = u >> 9;            // N-slice (slow axis -> L2-hot slice)
        const int r0 = um * 64;
        const int mtb = um * 4 + mw * 2;  // first global m16-tile for this warp

        float x2r[4];
#pragma unroll
        for (int mt = 0; mt < 2; mt++)
#pragma unroll
            for (int h = 0; h < 2; h++)
                x2r[mt * 2 + h] = g_x2[r0 + mw * 32 + mt * 16 + h * 8 + g];

        float bv[4];
        int   bi[4];
#pragma unroll
        for (int q = 0; q < 4; q++) { bv[q] = INFINITY; bi[q] = 0; }

        const int tbase = s * NSLC_T;
#pragma unroll 1
        for (int ch = 0; ch < 6; ch++)
            do_chunk<8>(Abase, Bbase, mtb, tbase + ch * 16 + nw * 8, x2r, bv, bi, l, t);
        do_chunk<2>(Abase, Bbase, mtb, tbase + 96 + nw * 2, x2r, bv, bi, l, t);

        // reduce across quad lanes (t)
#pragma unroll
        for (int q = 0; q < 4; q++) {
#pragma unroll
            for (int off = 1; off <= 2; off <<= 1) {
                float ov = __shfl_xor_sync(0xFFFFFFFFu, bv[q], off);
                int   oi = __shfl_xor_sync(0xFFFFFFFFu, bi[q], off);
                if (ov < bv[q] || (ov == bv[q] && oi < bi[q])) { bv[q] = ov; bi[q] = oi; }
            }
        }
        if (t == 0) {
#pragma unroll
            for (int q = 0; q < 4; q++) {
                int row = r0 + mw * 32 + (q >> 1) * 16 + (q & 1) * 8 + g;
                unsigned long long key =
                    ((unsigned long long)encf(bv[q]) << 32) | (unsigned long long)(uint32_t)bi[q];
                atomicMin(&g_best[row], key);
            }
        }
    }
}

// ---------------------------------------------------------------------------
// final: decode best key per row, write scalars + gather quantized row
// ---------------------------------------------------------------------------
__global__ void final_kernel(const float* __restrict__ centers, float* __restrict__ out) {
    int warp = (blockIdx.x * blockDim.x + threadIdx.x) >> 5;
    int lane = threadIdx.x & 31;
    if (warp >= BATCH) return;
    unsigned long long key = g_best[warp];
    int fi = (int)(uint32_t)(key & 0xFFFFFFFFull);
    float sq = decf((uint32_t)(key >> 32));
    if (lane == 0) {
        float* outAssign = out + (size_t)BATCH * DIM;
        float* outDist   = outAssign + BATCH;
        float* outClass  = outDist + BATCH;
        outAssign[warp] = (float)(fi % KC);
        outDist[warp]   = sqrtf(fmaxf(sq, 0.0f));
        outClass[warp]  = (float)(fi / KC);
    }
    float4 v = reinterpret_cast<const float4*>(centers)[(size_t)fi * 32 + lane];
    reinterpret_cast<float4*>(out)[(size_t)warp * 32 + lane] = v;
}

extern "C" void kernel_launch(void* const* d_in, const int* in_sizes, int n_in,
                              void* d_out, int out_size) {
    const float* x       = (const float*)d_in[0];
    const float* centers = (const float*)d_in[1];
    float* out = (float*)d_out;

    prep_ax_kernel<<<(BATCH * 32 + 255) / 256, 256>>>(x);
    prep_bc_kernel<<<(NCENT * 32 + 255) / 256, 256>>>(centers);
    vq_main<<<VQ_GRID, 128>>>();
    final_kernel<<<(BATCH * 32 + 255) / 256, 256>>>(centers, out);
}